// round 11
// baseline (speedup 1.0000x reference)
#include <cuda_runtime.h>
#include <cuda_bf16.h>
#include <cstdint>

typedef unsigned long long u64;

#define BB 4
#define NN 4096
#define MM 4096
#define MT 256            // threads per block == m's per block
#define NT 256            // n's per chunk (== MT: 1 prep per thread)
#define NQ (NT / 2)       // packed pairs per chunk = 128
#define NCHUNK (NN / NT)  // 16
#define MTILES (MM / MT)  // 16
#define NTILES (BB * MTILES)  // 64 tiles

#define EPSF     1e-8f
#define INV_LN2  1.4426950408889634f
// 1.5 * ln(2*3.14159)  (reference uses pi = 3.14159)
#define C_OFF    2.7568143383208773f

// transposed partials: g_part[m_global][ch] -- 16 contiguous floats per m
__device__ float g_part[BB * MM][NCHUNK];
__device__ float g_tile[NTILES];
__device__ unsigned g_tilecnt[NTILES];
__device__ unsigned g_count = 0;

// ---------------- packed f32x2 primitives ----------------
#define FMA2(d, a, b, c) asm("fma.rn.f32x2 %0, %1, %2, %3;"  : "=l"(d) : "l"(a), "l"(b), "l"(c))
#define ADD2(d, a, b)    asm("add.rn.f32x2 %0, %1, %2;"      : "=l"(d) : "l"(a), "l"(b))

__device__ __forceinline__ u64 pk(float lo, float hi) {
    u64 r;
    asm("mov.b64 %0, {%1, %2};" : "=l"(r) : "f"(lo), "f"(hi));
    return r;
}

__device__ __forceinline__ float ex2f(float x) {
    float r;
    asm("ex2.approx.f32 %0, %1;" : "=f"(r) : "f"(x));
    return r;
}

__device__ __forceinline__ float warp_sum(float v) {
#pragma unroll
    for (int o = 16; o > 0; o >>= 1)
        v += __shfl_xor_sync(0xFFFFFFFFu, v, o);
    return v;
}

// ------- main: fused prep + pair partial sums + fused full reduction -------
// Fences are single-thread only (post-__syncthreads), so the 262K-thread
// CCTL.IVALL storm that poisoned the R7/R9 fused kernels never happens.
__global__ __launch_bounds__(MT) void gmm_main_kernel(const float* __restrict__ xyz,
                                                      const float* __restrict__ sig,
                                                      const float* __restrict__ target,
                                                      float* __restrict__ out) {
    // per-q packed coefficient pairs: D12={cp,apx} D34={apy,bpz} D56={na,nb}
    __shared__ ulonglong2 sD12[NQ], sD34[NQ], sD56[NQ];
    __shared__ float wsum[MT / 32];
    __shared__ bool tileLast, gridLast;

    const int mt = blockIdx.x;     // 0..MTILES-1
    const int ch = blockIdx.y;     // 0..NCHUNK-1
    const int b  = blockIdx.z;     // 0..BB-1
    const int tid = threadIdx.x;
    const int lane = tid & 31;
    const int wrp  = tid >> 5;

    // ---- in-block prep: one n per thread (NT == MT) ----
    {
        const int n = b * NN + ch * NT + tid;
        float px = xyz[3 * n + 0], py = xyz[3 * n + 1], pz = xyz[3 * n + 2];
        float sxy = sig[2 * n + 0] + EPSF;
        float sz  = sig[2 * n + 1] + EPSF;
        float a  = __fdividef(0.5f * INV_LN2, sxy);   // log2-domain coefs
        float bz = __fdividef(0.5f * INV_LN2, sz);
        float c  = (-__logf(sxy) - 0.5f * __logf(sz) - C_OFF) * INV_LN2;
        float cp  = c - a * (px * px + py * py) - bz * (pz * pz);
        float apx = 2.0f * a * px;
        float apy = 2.0f * a * py;
        float bpz = 2.0f * bz * pz;

        const int q = tid >> 1, par = tid & 1;
        float* f12 = (float*)sD12;       // lanes: [4q+0/1]=cp_{e,o} [4q+2/3]=apx_{e,o}
        float* f34 = (float*)sD34;
        float* f56 = (float*)sD56;
        f12[4 * q + 0 + par] = cp;
        f12[4 * q + 2 + par] = apx;
        f34[4 * q + 0 + par] = apy;
        f34[4 * q + 2 + par] = bpz;
        f56[4 * q + 0 + par] = -a;
        f56[4 * q + 2 + par] = -bz;
    }

    // ---- per-m values ----
    const int m = mt * MT + tid;
    const float* tp = target + ((size_t)b * MM + m) * 3;
    const float tx = tp[0], ty = tp[1], tz = tp[2];
    const u64 TX  = pk(tx, tx);
    const u64 TY  = pk(ty, ty);
    const u64 TZ  = pk(tz, tz);
    const u64 ST  = pk(tx * tx + ty * ty, tx * tx + ty * ty);
    const u64 TZ2 = pk(tz * tz, tz * tz);

    __syncthreads();

    u64 acc = 0ull;                       // packed {0.0f, 0.0f}

#pragma unroll 8
    for (int j = 0; j < NQ; j++) {
        ulonglong2 D12 = sD12[j], D34 = sD34[j], D56 = sD56[j];
        u64 x;

        FMA2(x, D12.y, TX, D12.x);        // cp + apx*tx
        FMA2(x, D34.x, TY, x);            // + apy*ty
        FMA2(x, D34.y, TZ, x);            // + bpz*tz
        FMA2(x, D56.x, ST, x);            // - a*|txy|^2
        FMA2(x, D56.y, TZ2, x);           // - bz*tz^2      (x = lp/ln2, packed)

        float xlo, xhi;
        asm("mov.b64 {%0, %1}, %2;" : "=f"(xlo), "=f"(xhi) : "l"(x));
        // MUFU pipe: exp2; flushes huge-negative to 0 natively
        float e0 = ex2f(xlo);
        float e1 = ex2f(xhi);
        u64 pe = pk(e0, e1);              // repack (ALU)
        ADD2(acc, pe, acc);               // single fma-pipe accumulate
    }

    float a0 = __uint_as_float((unsigned)acc);
    float a1 = __uint_as_float((unsigned)(acc >> 32));
    g_part[b * MM + m][ch] = a0 + a1;     // transposed: coalesced for reader

    // ---- tile-level: last of the 16 chunk-blocks for this (b, mt) ----
    const int tile = b * MTILES + mt;
    __syncthreads();                      // CTA h-b edge: all STGs above -> tid0
    if (tid == 0) {
        __threadfence();                  // release (one thread only)
        tileLast = (atomicAdd(&g_tilecnt[tile], 1u) == NCHUNK - 1);
        if (tileLast) __threadfence();    // acquire for the reads below
    }
    __syncthreads();
    if (!tileLast) return;

    float nll;
    {
        // 16 contiguous floats per m: 4 x LDG.128, MLP=4, coalesced
        const float4* p = (const float4*)g_part[b * MM + m];
        float4 v0 = p[0], v1 = p[1], v2 = p[2], v3 = p[3];
        float s = ((v0.x + v0.y) + (v0.z + v0.w))
                + ((v1.x + v1.y) + (v1.z + v1.w))
                + ((v2.x + v2.y) + (v2.z + v2.w))
                + ((v3.x + v3.y) + (v3.z + v3.w));
        nll = -__logf(s);                 // nll = -ln(sum e^lp)
    }
    {
        float w = warp_sum(nll);          // fixed-order, deterministic
        if (lane == 0) wsum[wrp] = w;
    }
    __syncthreads();
    if (tid == 0) {
        float v = 0.0f;
#pragma unroll
        for (int k = 0; k < MT / 32; k++) v += wsum[k];
        g_tile[tile] = v;
        g_tilecnt[tile] = 0;              // reset for next graph replay
        __threadfence();                  // release
        gridLast = (atomicAdd(&g_count, 1u) == NTILES - 1);
        if (gridLast) __threadfence();    // acquire
    }
    __syncthreads();
    if (!gridLast) return;

    // ---- grid-level final: one warp combines 64 tile sums, fixed order ----
    if (wrp == 0) {
        float v = g_tile[lane] + g_tile[lane + 32];
#pragma unroll
        for (int o = 16; o > 0; o >>= 1)
            v += __shfl_xor_sync(0xFFFFFFFFu, v, o);
        if (lane == 0) {
            out[0] = v * (1.0f / (BB * MM));
            g_count = 0;                  // reset for next graph replay
        }
    }
}

extern "C" void kernel_launch(void* const* d_in, const int* in_sizes, int n_in,
                              void* d_out, int out_size) {
    const float* pred_xyz   = (const float*)d_in[0];  // [B, N, 3]
    const float* pred_sigma = (const float*)d_in[1];  // [B, N, 2]
    const float* target     = (const float*)d_in[2];  // [B, M, 3]
    float* out = (float*)d_out;

    dim3 grid(MTILES, NCHUNK, BB);
    gmm_main_kernel<<<grid, MT>>>(pred_xyz, pred_sigma, target, out);
}

// round 12
// speedup vs baseline: 1.1218x; 1.1218x over previous
#include <cuda_runtime.h>
#include <cuda_bf16.h>
#include <cstdint>

typedef unsigned long long u64;

#define BB 4
#define NN 4096
#define MM 4096
#define MT 128            // threads per block; each thread handles 2 m's
#define MPT 2             // m's per thread
#define MTILE (MT * MPT)  // 256 m's per tile
#define MTILES (MM / MTILE)   // 16
#define NT 256            // n's per chunk
#define NQ (NT / 2)       // packed pairs per chunk = 128
#define NCHUNK (NN / NT)  // 16
#define RED_BLOCKS 64
#define RED_T 256

#define EPSF     1e-8f
#define INV_LN2  1.4426950408889634f
// 1.5 * ln(2*3.14159)  (reference uses pi = 3.14159)
#define C_OFF    2.7568143383208773f

// transposed partials: g_part[m_global][ch] -- 16 contiguous floats per m
__device__ float g_part[BB * MM][NCHUNK];
__device__ float g_red[RED_BLOCKS];
__device__ unsigned g_count = 0;

// ---------------- packed f32x2 primitives ----------------
#define FMA2(d, a, b, c) asm("fma.rn.f32x2 %0, %1, %2, %3;"  : "=l"(d) : "l"(a), "l"(b), "l"(c))
#define ADD2(d, a, b)    asm("add.rn.f32x2 %0, %1, %2;"      : "=l"(d) : "l"(a), "l"(b))

__device__ __forceinline__ u64 pk(float lo, float hi) {
    u64 r;
    asm("mov.b64 %0, {%1, %2};" : "=l"(r) : "f"(lo), "f"(hi));
    return r;
}

__device__ __forceinline__ float ex2f(float x) {
    float r;
    asm("ex2.approx.f32 %0, %1;" : "=f"(r) : "f"(x));
    return r;
}

__device__ __forceinline__ float warp_sum(float v) {
#pragma unroll
    for (int o = 16; o > 0; o >>= 1)
        v += __shfl_xor_sync(0xFFFFFFFFu, v, o);
    return v;
}

// -------- main: fused prep + partial sums, 2 m's per thread ----------------
__global__ __launch_bounds__(MT) void gmm_main_kernel(const float* __restrict__ xyz,
                                                      const float* __restrict__ sig,
                                                      const float* __restrict__ target) {
    // per-q packed coefficient pairs: D12={cp,apx} D34={apy,bpz} D56={na,nb}
    __shared__ ulonglong2 sD12[NQ], sD34[NQ], sD56[NQ];

    const int mt = blockIdx.x;     // 0..MTILES-1
    const int ch = blockIdx.y;     // 0..NCHUNK-1
    const int b  = blockIdx.z;     // 0..BB-1
    const int tid = threadIdx.x;

    // ---- in-block prep: NT=256 n's with 128 threads (2 each) ----
    for (int jj = tid; jj < NT; jj += MT) {
        const int n = b * NN + ch * NT + jj;
        float px = xyz[3 * n + 0], py = xyz[3 * n + 1], pz = xyz[3 * n + 2];
        float sxy = sig[2 * n + 0] + EPSF;
        float sz  = sig[2 * n + 1] + EPSF;
        float a  = __fdividef(0.5f * INV_LN2, sxy);   // log2-domain coefs
        float bz = __fdividef(0.5f * INV_LN2, sz);
        float c  = (-__logf(sxy) - 0.5f * __logf(sz) - C_OFF) * INV_LN2;
        float cp  = c - a * (px * px + py * py) - bz * (pz * pz);
        float apx = 2.0f * a * px;
        float apy = 2.0f * a * py;
        float bpz = 2.0f * bz * pz;

        const int q = jj >> 1, par = jj & 1;
        float* f12 = (float*)sD12;       // lanes: [4q+0/1]=cp_{e,o} [4q+2/3]=apx_{e,o}
        float* f34 = (float*)sD34;
        float* f56 = (float*)sD56;
        f12[4 * q + 0 + par] = cp;
        f12[4 * q + 2 + par] = apx;
        f34[4 * q + 0 + par] = apy;
        f34[4 * q + 2 + par] = bpz;
        f56[4 * q + 0 + par] = -a;
        f56[4 * q + 2 + par] = -bz;
    }

    // ---- per-m values: two m's, 128 apart ----
    const int m0 = mt * MTILE + tid;
    const int m1 = m0 + MT;
    const float* tp0 = target + ((size_t)b * MM + m0) * 3;
    const float* tp1 = target + ((size_t)b * MM + m1) * 3;
    const float tx0 = tp0[0], ty0 = tp0[1], tz0 = tp0[2];
    const float tx1 = tp1[0], ty1 = tp1[1], tz1 = tp1[2];
    const u64 TX0  = pk(tx0, tx0), TX1 = pk(tx1, tx1);
    const u64 TY0  = pk(ty0, ty0), TY1 = pk(ty1, ty1);
    const u64 TZ0  = pk(tz0, tz0), TZ1 = pk(tz1, tz1);
    const u64 ST0  = pk(tx0 * tx0 + ty0 * ty0, tx0 * tx0 + ty0 * ty0);
    const u64 ST1  = pk(tx1 * tx1 + ty1 * ty1, tx1 * tx1 + ty1 * ty1);
    const u64 TZ20 = pk(tz0 * tz0, tz0 * tz0);
    const u64 TZ21 = pk(tz1 * tz1, tz1 * tz1);

    __syncthreads();

    u64 acc0 = 0ull, acc1 = 0ull;         // packed {0.0f, 0.0f} per m

#pragma unroll 4
    for (int j = 0; j < NQ; j++) {
        ulonglong2 D12 = sD12[j], D34 = sD34[j], D56 = sD56[j];
        u64 x0, x1;

        // two independent 5-FMA2 chains (ILP)
        FMA2(x0, D12.y, TX0, D12.x);
        FMA2(x1, D12.y, TX1, D12.x);
        FMA2(x0, D34.x, TY0, x0);
        FMA2(x1, D34.x, TY1, x1);
        FMA2(x0, D34.y, TZ0, x0);
        FMA2(x1, D34.y, TZ1, x1);
        FMA2(x0, D56.x, ST0, x0);
        FMA2(x1, D56.x, ST1, x1);
        FMA2(x0, D56.y, TZ20, x0);        // x = lp/ln2, packed over 2 n's
        FMA2(x1, D56.y, TZ21, x1);

        float a0, a1, b0, b1;
        asm("mov.b64 {%0, %1}, %2;" : "=f"(a0), "=f"(a1) : "l"(x0));
        asm("mov.b64 {%0, %1}, %2;" : "=f"(b0), "=f"(b1) : "l"(x1));
        // MUFU pipe: exp2; flushes huge-negative to 0 natively
        float e00 = ex2f(a0), e01 = ex2f(a1);
        float e10 = ex2f(b0), e11 = ex2f(b1);
        u64 p0 = pk(e00, e01);
        u64 p1 = pk(e10, e11);
        ADD2(acc0, p0, acc0);
        ADD2(acc1, p1, acc1);
    }

    {
        float v0 = __uint_as_float((unsigned)acc0);
        float v1 = __uint_as_float((unsigned)(acc0 >> 32));
        g_part[b * MM + m0][ch] = v0 + v1;
    }
    {
        float v0 = __uint_as_float((unsigned)acc1);
        float v1 = __uint_as_float((unsigned)(acc1 >> 32));
        g_part[b * MM + m1][ch] = v0 + v1;
    }
}

// ---------- reduction: 64 blocks x 256 thr; shuffle-based, 1 barrier -------
__global__ __launch_bounds__(RED_T) void gmm_red_kernel(float* __restrict__ out) {
    __shared__ float wsum[RED_T / 32];    // 8 per-warp sums
    __shared__ bool amLast;
    const int tid  = threadIdx.x;
    const int lane = tid & 31;
    const int wid  = tid >> 5;
    const int i = blockIdx.x * RED_T + tid;     // 0 .. BB*MM-1

    // 16 contiguous floats per m: 4 x LDG.128, MLP=4
    const float4* p = (const float4*)g_part[i];
    float4 v0 = p[0], v1 = p[1], v2 = p[2], v3 = p[3];
    float s = ((v0.x + v0.y) + (v0.z + v0.w))
            + ((v1.x + v1.y) + (v1.z + v1.w))
            + ((v2.x + v2.y) + (v2.z + v2.w))
            + ((v3.x + v3.y) + (v3.z + v3.w));
    float nll = -__logf(s);                     // nll = -ln(sum e^lp)

    float w = warp_sum(nll);                    // 5 shfl, no barriers
    if (lane == 0) wsum[wid] = w;
    __syncthreads();                            // the only block barrier

    if (wid == 0) {
        float v = (lane < RED_T / 32) ? wsum[lane] : 0.0f;
#pragma unroll
        for (int o = 4; o > 0; o >>= 1)
            v += __shfl_xor_sync(0xFFFFFFFFu, v, o);
        if (lane == 0) {
            g_red[blockIdx.x] = v;
            __threadfence();
            amLast = (atomicAdd(&g_count, 1u) == RED_BLOCKS - 1);
        }
    }
    __syncthreads();
    if (!amLast) return;

    // final: one warp combines 64 block sums (fixed tree order, deterministic)
    if (wid == 0) {
        float v = g_red[lane] + g_red[lane + 32];
#pragma unroll
        for (int o = 16; o > 0; o >>= 1)
            v += __shfl_xor_sync(0xFFFFFFFFu, v, o);
        if (lane == 0) {
            out[0] = v * (1.0f / (BB * MM));
            g_count = 0;                        // reset for next graph replay
        }
    }
}

extern "C" void kernel_launch(void* const* d_in, const int* in_sizes, int n_in,
                              void* d_out, int out_size) {
    const float* pred_xyz   = (const float*)d_in[0];  // [B, N, 3]
    const float* pred_sigma = (const float*)d_in[1];  // [B, N, 2]
    const float* target     = (const float*)d_in[2];  // [B, M, 3]
    float* out = (float*)d_out;

    dim3 grid(MTILES, NCHUNK, BB);
    gmm_main_kernel<<<grid, MT>>>(pred_xyz, pred_sigma, target);

    gmm_red_kernel<<<RED_BLOCKS, RED_T>>>(out);
}